// round 7
// baseline (speedup 1.0000x reference)
#include <cuda_runtime.h>
#include <cuda_bf16.h>
#include <cstdint>

// Problem constants
#define BATCH 8
#define CDIM 512
#define LDIM 4096
#define HEADS 8
#define DHEAD 64
#define HID 512            // HEADS*DHEAD
#define QKV_ROWS 1536      // 3*HID
#define CSPLIT 32          // n-splits for context partials

// ---------------------------------------------------------------------------
// Scratch (device globals; no allocation allowed)
// ---------------------------------------------------------------------------
__device__ float g_qkv[(size_t)BATCH * QKV_ROWS * LDIM];
__device__ signed char g_w1[(size_t)QKV_ROWS * CDIM];
__device__ signed char g_w2[(size_t)QKV_ROWS * CDIM];
__device__ float g_sw[QKV_ROWS];
__device__ signed char g_x1[(size_t)BATCH * LDIM * CDIM];
__device__ signed char g_x2[(size_t)BATCH * LDIM * CDIM];
__device__ float g_sx[(size_t)BATCH * LDIM];
__device__ signed char g_q1[(size_t)BATCH * LDIM * HID];
__device__ signed char g_q2[(size_t)BATCH * LDIM * HID];
__device__ float g_sq[(size_t)BATCH * LDIM];
__device__ float g_part[(size_t)CSPLIT * BATCH * HEADS * DHEAD * DHEAD];
__device__ float g_ctx[(size_t)BATCH * HEADS * DHEAD * DHEAD];
__device__ float g_M[(size_t)BATCH * HID * HID];
__device__ signed char g_M1[(size_t)BATCH * HID * HID];
__device__ signed char g_M2[(size_t)BATCH * HID * HID];
__device__ float g_sM[(size_t)BATCH * HID];

// ---------------------------------------------------------------------------
// PTX helpers (baseline sm_103 — mma.sync only, no tcgen05)
// ---------------------------------------------------------------------------
__device__ __forceinline__ uint32_t smem_to_u32(const void* smem_ptr) {
    uint32_t addr;
    asm("{ .reg .u64 tmp; cvta.to.shared.u64 tmp, %1; cvt.u32.u64 %0, tmp; }"
        : "=r"(addr) : "l"(smem_ptr));
    return addr;
}

#define SMEM_SWIZZLE_128B(byte_offset) \
    ((uint32_t)(byte_offset) ^ ((((uint32_t)(byte_offset)) >> 3) & 0x70u))

__device__ __forceinline__ void cp_async16(uint32_t dst, const void* src) {
    asm volatile("cp.async.cg.shared.global [%0], [%1], 16;"
                 :: "r"(dst), "l"(src) : "memory");
}
#define CP_ASYNC_COMMIT() asm volatile("cp.async.commit_group;" ::: "memory")
#define CP_ASYNC_WAIT(n)  asm volatile("cp.async.wait_group %0;" :: "n"(n) : "memory")

__device__ __forceinline__ void ldsm4(uint32_t* r, uint32_t addr) {
    asm volatile("ldmatrix.sync.aligned.m8n8.x4.shared.b16 {%0,%1,%2,%3}, [%4];"
                 : "=r"(r[0]), "=r"(r[1]), "=r"(r[2]), "=r"(r[3]) : "r"(addr));
}

__device__ __forceinline__ void mma_s8(int* d, const uint32_t* a, const uint32_t* b) {
    asm volatile(
        "mma.sync.aligned.m16n8k32.row.col.s32.s8.s8.s32 "
        "{%0,%1,%2,%3}, {%4,%5,%6,%7}, {%8,%9}, {%0,%1,%2,%3};"
        : "+r"(d[0]), "+r"(d[1]), "+r"(d[2]), "+r"(d[3])
        : "r"(a[0]), "r"(a[1]), "r"(a[2]), "r"(a[3]), "r"(b[0]), "r"(b[1]));
}

// ---------------------------------------------------------------------------
// Int8 2-limb GEMM (Ozaki-style): C[M,N] = sA[m]*sB[n]*(C11 + (C12+C21)/128)
// A,B given as int8 limb pairs, K-major. Tile 128x128, BK=128 bytes, 256 thr
// (2x4 warps, warp tile 64x32). 2-stage cp.async pipeline, 64KB/stage.
// ---------------------------------------------------------------------------
#define QSTAGE 65536
#define QOFF_A1 0
#define QOFF_A2 16384
#define QOFF_B1 32768
#define QOFF_B2 49152
#define QGEMM_SMEM (2 * QSTAGE)

__global__ __launch_bounds__(256, 1)
void i8_gemm_kernel(const signed char* __restrict__ A1,
                    const signed char* __restrict__ A2,
                    const signed char* __restrict__ B1,
                    const signed char* __restrict__ B2,
                    const float* __restrict__ sA,
                    const float* __restrict__ sB,
                    float* __restrict__ C,
                    int M, int N, int K,
                    long long aB, long long bB, long long cB,
                    long long saB, long long sbB,
                    const float* __restrict__ bias)
{
    extern __shared__ char smem[];
    const uint32_t sbase = smem_to_u32(smem);

    const int tid = threadIdx.x;
    const int wid = tid >> 5;
    const int lane = tid & 31;
    const int warp_m = wid >> 2;       // 0..1 (64 rows)
    const int warp_n = wid & 3;        // 0..3 (32 cols)

    const int b = blockIdx.z;
    A1 += (long long)b * aB;  A2 += (long long)b * aB;
    B1 += (long long)b * bB;  B2 += (long long)b * bB;
    C  += (long long)b * cB;
    sA += (long long)b * saB;
    sB += (long long)b * sbB;

    const int bm = blockIdx.y * 128;
    const int bn = blockIdx.x * 128;

    int accm[4][4][4], accc[4][4][4];
#pragma unroll
    for (int i = 0; i < 4; i++)
#pragma unroll
        for (int j = 0; j < 4; j++)
#pragma unroll
            for (int r = 0; r < 4; r++) { accm[i][j][r] = 0; accc[i][j][r] = 0; }

    const int nchunk = K >> 7;  // 128 int8 per chunk

    auto load_chunk = [&](int ch, int stage) {
        const int k0 = ch << 7;
        const uint32_t sb = sbase + stage * QSTAGE;
#pragma unroll
        for (int it = 0; it < 4; it++) {
            const int g = it * 256 + tid;   // 0..1023 granules (16B)
            const int row = g >> 3;
            const int gr = g & 7;
            const uint32_t sw = SMEM_SWIZZLE_128B(row * 128 + gr * 16);
            const long long aoff = (long long)(bm + row) * K + k0 + gr * 16;
            const long long boff = (long long)(bn + row) * K + k0 + gr * 16;
            cp_async16(sb + QOFF_A1 + sw, A1 + aoff);
            cp_async16(sb + QOFF_A2 + sw, A2 + aoff);
            cp_async16(sb + QOFF_B1 + sw, B1 + boff);
            cp_async16(sb + QOFF_B2 + sw, B2 + boff);
        }
        CP_ASYNC_COMMIT();
    };

    load_chunk(0, 0);

    for (int ch = 0; ch < nchunk; ch++) {
        if (ch + 1 < nchunk) {
            load_chunk(ch + 1, (ch + 1) & 1);
            CP_ASYNC_WAIT(1);
        } else {
            CP_ASYNC_WAIT(0);
        }
        __syncthreads();

        const uint32_t sb = sbase + (ch & 1) * QSTAGE;
#pragma unroll
        for (int ks = 0; ks < 4; ks++) {     // K=32 bytes per step
            uint32_t b1r[8], b2r[8];
#pragma unroll
            for (int p = 0; p < 2; p++) {
                const int r = warp_n * 32 + p * 16 + ((lane >> 4) & 1) * 8 + (lane & 7);
                const int cb = ks * 32 + ((lane >> 3) & 1) * 16;
                const uint32_t adr = sb + QOFF_B1 + SMEM_SWIZZLE_128B(r * 128 + cb);
                ldsm4(b1r + p * 4, adr);
                ldsm4(b2r + p * 4, adr + (QOFF_B2 - QOFF_B1));
            }
#pragma unroll
            for (int i = 0; i < 4; i++) {
                const int r = warp_m * 64 + i * 16 + ((lane >> 3) & 1) * 8 + (lane & 7);
                const int cb = ks * 32 + ((lane >> 4) & 1) * 16;
                const uint32_t adr = sb + QOFF_A1 + SMEM_SWIZZLE_128B(r * 128 + cb);
                uint32_t a1r[4], a2r[4];
                ldsm4(a1r, adr);
                ldsm4(a2r, adr + (QOFF_A2 - QOFF_A1));
#pragma unroll
                for (int j = 0; j < 4; j++) {
                    const int base = (j >> 1) * 4 + (j & 1) * 2;
                    mma_s8(accm[i][j], a1r, b1r + base);
                    mma_s8(accc[i][j], a1r, b2r + base);
                    mma_s8(accc[i][j], a2r, b1r + base);
                }
            }
        }
        __syncthreads();
    }

    // Epilogue: scale limbs, add bias, store float2
#pragma unroll
    for (int i = 0; i < 4; i++) {
        const int m0 = bm + warp_m * 64 + i * 16 + (lane >> 2);
        const float sa0 = sA[m0];
        const float sa1 = sA[m0 + 8];
        const float bv0 = bias ? bias[m0] : 0.0f;
        const float bv1 = bias ? bias[m0 + 8] : 0.0f;
#pragma unroll
        for (int j = 0; j < 4; j++) {
            const int n0 = bn + warp_n * 32 + j * 8 + (lane & 3) * 2;
            const float2 s2 = *(const float2*)(sB + n0);
            float2 v0, v1;
            v0.x = ((float)accm[i][j][0] + (float)accc[i][j][0] * 0.0078125f) * sa0 * s2.x + bv0;
            v0.y = ((float)accm[i][j][1] + (float)accc[i][j][1] * 0.0078125f) * sa0 * s2.y + bv0;
            v1.x = ((float)accm[i][j][2] + (float)accc[i][j][2] * 0.0078125f) * sa1 * s2.x + bv1;
            v1.y = ((float)accm[i][j][3] + (float)accc[i][j][3] * 0.0078125f) * sa1 * s2.y + bv1;
            *(float2*)(C + (long long)m0 * N + n0) = v0;
            *(float2*)(C + (long long)(m0 + 8) * N + n0) = v1;
        }
    }
}

// ---------------------------------------------------------------------------
// Per-row quantize: in fp32 [rows][512] -> limbs int8 + scale (max/127)
// ---------------------------------------------------------------------------
__global__ __launch_bounds__(256) void quant_rows_kernel(
    const float* __restrict__ in, signed char* __restrict__ q1,
    signed char* __restrict__ q2, float* __restrict__ scale)
{
    const long long row = blockIdx.x;
    in += row * 512;  q1 += row * 512;  q2 += row * 512;

    __shared__ float red[256];
    const int tid = threadIdx.x;
    const float v0 = in[tid];
    const float v1 = in[tid + 256];
    red[tid] = fmaxf(fabsf(v0), fabsf(v1));
    __syncthreads();
    for (int s = 128; s > 0; s >>= 1) {
        if (tid < s) red[tid] = fmaxf(red[tid], red[tid + s]);
        __syncthreads();
    }
    const float m = fmaxf(red[0], 1e-20f);
    if (tid == 0) scale[row] = m * (1.0f / 127.0f);
    const float si = 127.0f / m;

    float a = rintf(v0 * si);
    q1[tid] = (signed char)(int)a;
    q2[tid] = (signed char)(int)rintf((v0 * si - a) * 128.0f);
    a = rintf(v1 * si);
    q1[tid + 256] = (signed char)(int)a;
    q2[tid + 256] = (signed char)(int)rintf((v1 * si - a) * 128.0f);
}

// ---------------------------------------------------------------------------
// Transpose + quantize: in fp32 [512 rows, LDIM cols] -> per output row l
// (512 values) scale + int8 limbs [LDIM][512]. 32 l's per block.
// ---------------------------------------------------------------------------
__global__ __launch_bounds__(256) void transpose_quant_kernel(
    const float* __restrict__ in, long long inBatch,
    signed char* __restrict__ q1, signed char* __restrict__ q2,
    float* __restrict__ scale, long long outBatch, long long scaleBatch)
{
    extern __shared__ float t[];   // [512][33]
    __shared__ float red[32][8];
    __shared__ float sinv[32];

    const int b = blockIdx.z;
    const int l0 = blockIdx.x * 32;
    in += (long long)b * inBatch;
    q1 += (long long)b * outBatch;
    q2 += (long long)b * outBatch;
    scale += (long long)b * scaleBatch;

    const int tid = threadIdx.x;
    const int lc = tid & 31;
    for (int r = tid >> 5; r < 512; r += 8)
        t[r * 33 + lc] = in[(long long)r * LDIM + l0 + lc];
    __syncthreads();

    const int l = tid >> 3;
    const int part = tid & 7;
    float m = 0.0f;
    for (int k = 0; k < 64; k++) {
        const int r = part + k * 8;            // strided: conflict-free
        m = fmaxf(m, fabsf(t[r * 33 + l]));
    }
    red[l][part] = m;
    __syncthreads();
    if (part == 0) {
#pragma unroll
        for (int u = 1; u < 8; u++) m = fmaxf(m, red[l][u]);
        m = fmaxf(m, 1e-20f);
        sinv[l] = 127.0f / m;
        scale[l0 + l] = m * (1.0f / 127.0f);
    }
    __syncthreads();

    const float si = sinv[l];
    signed char* o1 = q1 + (long long)(l0 + l) * 512;
    signed char* o2 = q2 + (long long)(l0 + l) * 512;
    for (int k = 0; k < 16; k++) {
        const int r0 = part * 64 + k * 4;
        char4 c1, c2;
        float v, a;
        v = t[(r0 + 0) * 33 + l] * si;  a = rintf(v);
        c1.x = (signed char)(int)a;  c2.x = (signed char)(int)rintf((v - a) * 128.0f);
        v = t[(r0 + 1) * 33 + l] * si;  a = rintf(v);
        c1.y = (signed char)(int)a;  c2.y = (signed char)(int)rintf((v - a) * 128.0f);
        v = t[(r0 + 2) * 33 + l] * si;  a = rintf(v);
        c1.z = (signed char)(int)a;  c2.z = (signed char)(int)rintf((v - a) * 128.0f);
        v = t[(r0 + 3) * 33 + l] * si;  a = rintf(v);
        c1.w = (signed char)(int)a;  c2.w = (signed char)(int)rintf((v - a) * 128.0f);
        *(char4*)(o1 + r0) = c1;
        *(char4*)(o2 + r0) = c2;
    }
}

// ---------------------------------------------------------------------------
// Row softmax over L=4096 on k rows (rows 512..1023 of each batch's qkv)
// ---------------------------------------------------------------------------
__global__ __launch_bounds__(256) void softmax_kernel()
{
    const int row = blockIdx.x;
    const int b = row >> 9;
    const int r = row & 511;
    float* p = g_qkv + (long long)b * QKV_ROWS * LDIM + (long long)(HID + r) * LDIM;

    const int tid = threadIdx.x;
    __shared__ float red[256];

    float4 v[4];
#pragma unroll
    for (int i = 0; i < 4; i++)
        v[i] = *(const float4*)(p + i * 1024 + tid * 4);

    float vmax = -1e30f;
#pragma unroll
    for (int i = 0; i < 4; i++)
        vmax = fmaxf(vmax, fmaxf(fmaxf(v[i].x, v[i].y), fmaxf(v[i].z, v[i].w)));
    red[tid] = vmax;
    __syncthreads();
    for (int s = 128; s > 0; s >>= 1) {
        if (tid < s) red[tid] = fmaxf(red[tid], red[tid + s]);
        __syncthreads();
    }
    vmax = red[0];
    __syncthreads();

    float lsum = 0.0f;
#pragma unroll
    for (int i = 0; i < 4; i++) {
        v[i].x = expf(v[i].x - vmax); lsum += v[i].x;
        v[i].y = expf(v[i].y - vmax); lsum += v[i].y;
        v[i].z = expf(v[i].z - vmax); lsum += v[i].z;
        v[i].w = expf(v[i].w - vmax); lsum += v[i].w;
    }
    red[tid] = lsum;
    __syncthreads();
    for (int s = 128; s > 0; s >>= 1) {
        if (tid < s) red[tid] += red[tid + s];
        __syncthreads();
    }
    const float inv = 1.0f / red[0];

#pragma unroll
    for (int i = 0; i < 4; i++) {
        v[i].x *= inv; v[i].y *= inv; v[i].z *= inv; v[i].w *= inv;
        *(float4*)(p + i * 1024 + tid * 4) = v[i];
    }
}

// ---------------------------------------------------------------------------
// Context partials + reduce + fold (fp32, unchanged)
// ---------------------------------------------------------------------------
__global__ __launch_bounds__(256) void context_partial_kernel()
{
    const int split = blockIdx.x;
    const int bh = blockIdx.y;
    const int b = bh >> 3, h = bh & 7;

    const float* kbase = g_qkv + (long long)b * QKV_ROWS * LDIM + (long long)(HID + h * DHEAD) * LDIM;
    const float* vbase = g_qkv + (long long)b * QKV_ROWS * LDIM + (long long)(2 * HID + h * DHEAD) * LDIM;

    __shared__ float Ks[64][65];
    __shared__ float Vs[64][65];

    const int tid = threadIdx.x;
    const int td = (tid >> 4) * 4;
    const int te = (tid & 15) * 4;

    float acc[4][4];
#pragma unroll
    for (int i = 0; i < 4; i++)
#pragma unroll
        for (int j = 0; j < 4; j++) acc[i][j] = 0.0f;

    const int chunk = LDIM / CSPLIT;
    for (int sub = 0; sub < chunk / 64; sub++) {
        const int n0 = split * chunk + sub * 64;
        for (int i = tid; i < 1024; i += 256) {
            const int r = i >> 4, c = (i & 15) * 4;
            float4 kv = *(const float4*)(kbase + (long long)r * LDIM + n0 + c);
            Ks[r][c] = kv.x; Ks[r][c + 1] = kv.y; Ks[r][c + 2] = kv.z; Ks[r][c + 3] = kv.w;
            float4 vv = *(const float4*)(vbase + (long long)r * LDIM + n0 + c);
            Vs[r][c] = vv.x; Vs[r][c + 1] = vv.y; Vs[r][c + 2] = vv.z; Vs[r][c + 3] = vv.w;
        }
        __syncthreads();

#pragma unroll 8
        for (int n = 0; n < 64; n++) {
            float kr[4], vr[4];
#pragma unroll
            for (int i = 0; i < 4; i++) kr[i] = Ks[td + i][n];
#pragma unroll
            for (int j = 0; j < 4; j++) vr[j] = Vs[te + j][n];
#pragma unroll
            for (int i = 0; i < 4; i++)
#pragma unroll
                for (int j = 0; j < 4; j++)
                    acc[i][j] = fmaf(kr[i], vr[j], acc[i][j]);
        }
        __syncthreads();
    }

    float* pout = g_part + ((long long)split * 64 + bh) * (DHEAD * DHEAD);
#pragma unroll
    for (int i = 0; i < 4; i++)
#pragma unroll
        for (int j = 0; j < 4; j++)
            pout[(td + i) * DHEAD + (te + j)] = acc[i][j];
}

__global__ __launch_bounds__(256) void reduce_ctx_kernel()
{
    const int i = blockIdx.x * blockDim.x + threadIdx.x;
    const int total = BATCH * HEADS * DHEAD * DHEAD;
    if (i < total) {
        float s = 0.0f;
#pragma unroll
        for (int sp = 0; sp < CSPLIT; sp++)
            s += g_part[(long long)sp * total + i];
        g_ctx[i] = s;
    }
}

__global__ __launch_bounds__(256) void fold_kernel(const float* __restrict__ w_out)
{
    const int oc = blockIdx.x;
    const int bh = blockIdx.y;
    const int b = bh >> 3, h = bh & 7;

    __shared__ float cs[64][65];
    __shared__ float ws[64][65];

    const int tid = threadIdx.x;
    for (int i = tid; i < 4096; i += 256) {
        const int d = i >> 6, e = i & 63;
        cs[d][e] = g_ctx[((long long)bh * 64 + d) * 64 + e];
    }
    for (int i = tid; i < 4096; i += 256) {
        const int r = i >> 6, e = i & 63;
        ws[r][e] = w_out[(long long)(oc * 64 + r) * CDIM + h * 64 + e];
    }
    __syncthreads();

    const int d = tid & 63;
    const int r0 = (tid >> 6) * 16;
    for (int rr = 0; rr < 16; rr++) {
        float s = 0.0f;
#pragma unroll 8
        for (int e = 0; e < 64; e++)
            s = fmaf(ws[r0 + rr][e], cs[d][e], s);
        g_M[((long long)b * HID + oc * 64 + r0 + rr) * HID + h * 64 + d] = s;
    }
}

// ---------------------------------------------------------------------------
extern "C" void kernel_launch(void* const* d_in, const int* in_sizes, int n_in,
                              void* d_out, int out_size)
{
    const float* x     = (const float*)d_in[0];   // [8, 512, 4096]
    const float* w_qkv = (const float*)d_in[1];   // [1536, 512]
    const float* w_out = (const float*)d_in[2];   // [512, 512]
    const float* b_out = (const float*)d_in[3];   // [512]
    float* out = (float*)d_out;                   // [8, 512, 4096]

    float *p_qkv, *p_M, *p_sw, *p_sx, *p_sq, *p_sM;
    signed char *p_w1, *p_w2, *p_x1, *p_x2, *p_q1, *p_q2, *p_M1, *p_M2;
    cudaGetSymbolAddress((void**)&p_qkv, g_qkv);
    cudaGetSymbolAddress((void**)&p_M, g_M);
    cudaGetSymbolAddress((void**)&p_w1, g_w1);
    cudaGetSymbolAddress((void**)&p_w2, g_w2);
    cudaGetSymbolAddress((void**)&p_sw, g_sw);
    cudaGetSymbolAddress((void**)&p_x1, g_x1);
    cudaGetSymbolAddress((void**)&p_x2, g_x2);
    cudaGetSymbolAddress((void**)&p_sx, g_sx);
    cudaGetSymbolAddress((void**)&p_q1, g_q1);
    cudaGetSymbolAddress((void**)&p_q2, g_q2);
    cudaGetSymbolAddress((void**)&p_sq, g_sq);
    cudaGetSymbolAddress((void**)&p_M1, g_M1);
    cudaGetSymbolAddress((void**)&p_M2, g_M2);
    cudaGetSymbolAddress((void**)&p_sM, g_sM);

    cudaFuncSetAttribute(i8_gemm_kernel,
                         cudaFuncAttributeMaxDynamicSharedMemorySize, QGEMM_SMEM);
    cudaFuncSetAttribute(transpose_quant_kernel,
                         cudaFuncAttributeMaxDynamicSharedMemorySize, 512 * 33 * 4);

    // 0) quantize W; transpose+quantize X
    quant_rows_kernel<<<QKV_ROWS, 256>>>(w_qkv, p_w1, p_w2, p_sw);
    transpose_quant_kernel<<<dim3(LDIM / 32, 1, BATCH), 256, 512 * 33 * 4>>>(
        x, (long long)CDIM * LDIM, p_x1, p_x2, p_sx,
        (long long)LDIM * CDIM, (long long)LDIM);

    // 1) qkv = W @ x  (int8 2-limb tensor cores)
    i8_gemm_kernel<<<dim3(LDIM / 128, QKV_ROWS / 128, BATCH), 256, QGEMM_SMEM>>>(
        p_w1, p_w2, p_x1, p_x2, p_sw, p_sx, p_qkv,
        QKV_ROWS, LDIM, CDIM,
        0LL, (long long)LDIM * CDIM, (long long)QKV_ROWS * LDIM,
        0LL, (long long)LDIM, nullptr);

    // 2) transpose+quantize q (rows 0..511 of qkv per batch)
    transpose_quant_kernel<<<dim3(LDIM / 32, 1, BATCH), 256, 512 * 33 * 4>>>(
        p_qkv, (long long)QKV_ROWS * LDIM, p_q1, p_q2, p_sq,
        (long long)LDIM * HID, (long long)LDIM);

    // 3) softmax over L on k rows
    softmax_kernel<<<BATCH * HID, 256>>>();

    // 4) context partials + deterministic reduce
    context_partial_kernel<<<dim3(CSPLIT, BATCH * HEADS), 256>>>();
    {
        const int total = BATCH * HEADS * DHEAD * DHEAD;
        reduce_ctx_kernel<<<(total + 255) / 256, 256>>>();
    }

    // 5) fold w_out with context -> per-batch M; quantize M rows
    fold_kernel<<<dim3(8, BATCH * HEADS), 256>>>(w_out);
    quant_rows_kernel<<<BATCH * HID, 256>>>(p_M, p_M1, p_M2, p_sM);

    // 6) out = M @ q + b_out  (int8 2-limb tensor cores)
    i8_gemm_kernel<<<dim3(LDIM / 128, HID / 128, BATCH), 256, QGEMM_SMEM>>>(
        p_M1, p_M2, p_q1, p_q2, p_sM, p_sq, out,
        HID, LDIM, HID,
        (long long)HID * HID, (long long)LDIM * HID, (long long)HID * LDIM,
        (long long)HID, (long long)LDIM, b_out);
}

// round 8
// speedup vs baseline: 2.4838x; 2.4838x over previous
#include <cuda_runtime.h>
#include <cuda_bf16.h>
#include <cstdint>

// Problem constants
#define BATCH 8
#define CDIM 512
#define LDIM 4096
#define HEADS 8
#define DHEAD 64
#define HID 512            // HEADS*DHEAD
#define QKV_ROWS 1536      // 3*HID
#define CSPLIT 32          // n-splits for context partials

// ---------------------------------------------------------------------------
// Scratch (device globals; no allocation allowed)
// ---------------------------------------------------------------------------
__device__ float g_qkv[(size_t)BATCH * QKV_ROWS * LDIM];
__device__ __nv_bfloat16 g_xt_hi[(size_t)BATCH * LDIM * CDIM];
__device__ __nv_bfloat16 g_xt_lo[(size_t)BATCH * LDIM * CDIM];
__device__ __nv_bfloat16 g_qt_hi[(size_t)BATCH * LDIM * HID];
__device__ __nv_bfloat16 g_qt_lo[(size_t)BATCH * LDIM * HID];
__device__ __nv_bfloat16 g_w_hi[(size_t)QKV_ROWS * CDIM];
__device__ __nv_bfloat16 g_w_lo[(size_t)QKV_ROWS * CDIM];
__device__ float g_part[(size_t)CSPLIT * BATCH * HEADS * DHEAD * DHEAD];
__device__ float g_ctx[(size_t)BATCH * HEADS * DHEAD * DHEAD];
__device__ float g_M[(size_t)BATCH * HID * HID];
__device__ __nv_bfloat16 g_M_hi[(size_t)BATCH * HID * HID];
__device__ __nv_bfloat16 g_M_lo[(size_t)BATCH * HID * HID];

// ---------------------------------------------------------------------------
// PTX helpers (baseline sm_103 — mma.sync bf16 only; no tcgen05, no int8)
// ---------------------------------------------------------------------------
__device__ __forceinline__ uint32_t smem_to_u32(const void* smem_ptr) {
    uint32_t addr;
    asm("{ .reg .u64 tmp; cvta.to.shared.u64 tmp, %1; cvt.u32.u64 %0, tmp; }"
        : "=r"(addr) : "l"(smem_ptr));
    return addr;
}

#define SMEM_SWIZZLE_128B(byte_offset) \
    ((uint32_t)(byte_offset) ^ ((((uint32_t)(byte_offset)) >> 3) & 0x70u))

__device__ __forceinline__ void cp_async16(uint32_t dst, const void* src) {
    asm volatile("cp.async.cg.shared.global [%0], [%1], 16;"
                 :: "r"(dst), "l"(src) : "memory");
}
#define CP_ASYNC_COMMIT() asm volatile("cp.async.commit_group;" ::: "memory")
#define CP_ASYNC_WAIT(n)  asm volatile("cp.async.wait_group %0;" :: "n"(n) : "memory")

__device__ __forceinline__ void ldsm4(uint32_t* r, uint32_t addr) {
    asm volatile("ldmatrix.sync.aligned.m8n8.x4.shared.b16 {%0,%1,%2,%3}, [%4];"
                 : "=r"(r[0]), "=r"(r[1]), "=r"(r[2]), "=r"(r[3]) : "r"(addr));
}

__device__ __forceinline__ void mma_bf16(float* c, const uint32_t* a, const uint32_t* b) {
    asm volatile(
        "mma.sync.aligned.m16n8k16.row.col.f32.bf16.bf16.f32 "
        "{%0,%1,%2,%3}, {%4,%5,%6,%7}, {%8,%9}, {%0,%1,%2,%3};"
        : "+f"(c[0]), "+f"(c[1]), "+f"(c[2]), "+f"(c[3])
        : "r"(a[0]), "r"(a[1]), "r"(a[2]), "r"(a[3]), "r"(b[0]), "r"(b[1]));
}

// ---------------------------------------------------------------------------
// Persistent split-bf16 HMMA GEMM: C[M,N] = A[M,K] @ B[N,K]^T (+row bias)
// K must be 512 (8 chunks of BK=64). Tile 128x128, 256 threads,
// 2x4 warps (warp tile 64x32). 3-stage cp.async pipeline running
// CONTINUOUSLY across tiles (grid = #SMs, each CTA strides over tiles).
// ---------------------------------------------------------------------------
#define STAGE_BYTES 65536
#define OFF_AHI 0
#define OFF_ALO 16384
#define OFF_BHI 32768
#define OFF_BLO 49152
#define GEMM_SMEM (3 * STAGE_BYTES)
#define CHUNKS_PER_TILE 8    // K=512 / BK=64

__global__ __launch_bounds__(256, 1)
void mma_gemm_persistent(const __nv_bfloat16* __restrict__ Ahi,
                         const __nv_bfloat16* __restrict__ Alo,
                         const __nv_bfloat16* __restrict__ Bhi,
                         const __nv_bfloat16* __restrict__ Blo,
                         float* __restrict__ C,
                         int ntm, int ntn, int nb, int N, int K,
                         long long sA, long long sB, long long sC,
                         const float* __restrict__ bias)
{
    extern __shared__ char smem[];
    const uint32_t sbase = smem_to_u32(smem);

    const int tid = threadIdx.x;
    const int wid = tid >> 5;
    const int lane = tid & 31;
    const int warp_m = wid >> 2;       // 0..1 (64 rows)
    const int warp_n = wid & 3;        // 0..3 (32 cols)

    const int ntiles = ntm * ntn * nb;
    const int my_ntiles = (ntiles - (int)blockIdx.x + (int)gridDim.x - 1) / (int)gridDim.x;
    const int my_nchunks = my_ntiles * CHUNKS_PER_TILE;

    // --- chunk loader: k-th chunk of this CTA's tile sequence ---
    auto load_chunk = [&](int k) {
        const int t = k >> 3;
        const int tile_lin = (int)blockIdx.x + t * (int)gridDim.x;
        if (tile_lin >= ntiles) { CP_ASYNC_COMMIT(); return; }
        const int nx = tile_lin % ntn;
        const int rest = tile_lin / ntn;
        const int my = rest % ntm;
        const int b = rest / ntm;
        const int bm = my << 7;
        const int bn = nx << 7;
        const int k0 = (k & 7) << 6;
        const __nv_bfloat16* pAhi = Ahi + (long long)b * sA;
        const __nv_bfloat16* pAlo = Alo + (long long)b * sA;
        const __nv_bfloat16* pBhi = Bhi + (long long)b * sB;
        const __nv_bfloat16* pBlo = Blo + (long long)b * sB;
        const uint32_t sb = sbase + (uint32_t)(k % 3) * STAGE_BYTES;
#pragma unroll
        for (int it = 0; it < 4; it++) {
            const int g = it * 256 + tid;     // 0..1023 granules (16B)
            const int row = g >> 3;
            const int gr = g & 7;
            const uint32_t sw = SMEM_SWIZZLE_128B(row * 128 + gr * 16);
            const long long aoff = (long long)(bm + row) * K + k0 + gr * 8;
            const long long boff = (long long)(bn + row) * K + k0 + gr * 8;
            cp_async16(sb + OFF_AHI + sw, pAhi + aoff);
            cp_async16(sb + OFF_ALO + sw, pAlo + aoff);
            cp_async16(sb + OFF_BHI + sw, pBhi + boff);
            cp_async16(sb + OFF_BLO + sw, pBlo + boff);
        }
        CP_ASYNC_COMMIT();
    };

    float acc[4][4][4];
#pragma unroll
    for (int i = 0; i < 4; i++)
#pragma unroll
        for (int j = 0; j < 4; j++)
#pragma unroll
            for (int r = 0; r < 4; r++) acc[i][j][r] = 0.0f;

    load_chunk(0);
    load_chunk(1);

    for (int k = 0; k < my_nchunks; k++) {
        CP_ASYNC_WAIT(1);
        __syncthreads();

        const uint32_t sb = sbase + (uint32_t)(k % 3) * STAGE_BYTES;
#pragma unroll
        for (int ks = 0; ks < 4; ks++) {
            uint32_t bhi[8], blo[8];
#pragma unroll
            for (int p = 0; p < 2; p++) {
                const int r = warp_n * 32 + p * 16 + ((lane >> 4) & 1) * 8 + (lane & 7);
                const int cb = ks * 32 + ((lane >> 3) & 1) * 16;
                const uint32_t adr = sb + OFF_BHI + SMEM_SWIZZLE_128B(r * 128 + cb);
                ldsm4(bhi + p * 4, adr);
                ldsm4(blo + p * 4, adr + (OFF_BLO - OFF_BHI));
            }
#pragma unroll
            for (int i = 0; i < 4; i++) {
                const int r = warp_m * 64 + i * 16 + ((lane >> 3) & 1) * 8 + (lane & 7);
                const int cb = ks * 32 + ((lane >> 4) & 1) * 16;
                const uint32_t adr = sb + OFF_AHI + SMEM_SWIZZLE_128B(r * 128 + cb);
                uint32_t ahi[4], alo[4];
                ldsm4(ahi, adr);
                ldsm4(alo, adr + (OFF_ALO - OFF_AHI));
#pragma unroll
                for (int j = 0; j < 4; j++) {
                    const uint32_t* bh = bhi + (j >> 1) * 4 + (j & 1) * 2;
                    const uint32_t* bl = blo + (j >> 1) * 4 + (j & 1) * 2;
                    mma_bf16(acc[i][j], ahi, bh);
                    mma_bf16(acc[i][j], ahi, bl);
                    mma_bf16(acc[i][j], alo, bh);
                }
            }
        }

        // Prefetch 2 chunks ahead (3-stage rotation => no WAR hazard)
        load_chunk(k + 2);

        if ((k & 7) == 7) {
            // Tile finished: epilogue + reset accumulators
            const int t = k >> 3;
            const int tile_lin = (int)blockIdx.x + t * (int)gridDim.x;
            const int nx = tile_lin % ntn;
            const int rest = tile_lin / ntn;
            const int my = rest % ntm;
            const int b = rest / ntm;
            const int bm = my << 7;
            const int bn = nx << 7;
            float* pC = C + (long long)b * sC;
#pragma unroll
            for (int i = 0; i < 4; i++) {
                const int m0 = bm + warp_m * 64 + i * 16 + (lane >> 2);
                const float bv0 = bias ? bias[m0] : 0.0f;
                const float bv1 = bias ? bias[m0 + 8] : 0.0f;
#pragma unroll
                for (int j = 0; j < 4; j++) {
                    const int n0 = bn + warp_n * 32 + j * 8 + (lane & 3) * 2;
                    float2 v0, v1;
                    v0.x = acc[i][j][0] + bv0;  v0.y = acc[i][j][1] + bv0;
                    v1.x = acc[i][j][2] + bv1;  v1.y = acc[i][j][3] + bv1;
                    *(float2*)(pC + (long long)m0 * N + n0) = v0;
                    *(float2*)(pC + (long long)(m0 + 8) * N + n0) = v1;
                    acc[i][j][0] = 0.0f; acc[i][j][1] = 0.0f;
                    acc[i][j][2] = 0.0f; acc[i][j][3] = 0.0f;
                }
            }
        }
    }
}

// ---------------------------------------------------------------------------
// Transpose + split-convert: in fp32 [R, L] -> out_hi/out_lo bf16 [L, R]
// ---------------------------------------------------------------------------
__global__ __launch_bounds__(256) void transpose_convert_kernel(
    const float* __restrict__ in,
    __nv_bfloat16* __restrict__ out_hi, __nv_bfloat16* __restrict__ out_lo,
    int R, int L, long long inStride, long long outStride)
{
    const int b = blockIdx.z;
    in += (long long)b * inStride;
    out_hi += (long long)b * outStride;
    out_lo += (long long)b * outStride;

    __shared__ float t[32][33];
    const int r0 = blockIdx.y * 32;
    const int c0 = blockIdx.x * 32;
    const int tx = threadIdx.x & 31;
    const int ty = threadIdx.x >> 5;

#pragma unroll
    for (int i = 0; i < 4; i++)
        t[ty + i * 8][tx] = in[(long long)(r0 + ty + i * 8) * L + c0 + tx];
    __syncthreads();
#pragma unroll
    for (int i = 0; i < 4; i++) {
        const float v = t[tx][ty + i * 8];
        const __nv_bfloat16 hi = __float2bfloat16(v);
        const float lo = v - __bfloat162float(hi);
        const long long o = (long long)(c0 + ty + i * 8) * R + r0 + tx;
        out_hi[o] = hi;
        out_lo[o] = __float2bfloat16(lo);
    }
}

// Plain split-convert
__global__ __launch_bounds__(256) void convert_split_kernel(
    const float* __restrict__ in,
    __nv_bfloat16* __restrict__ hi, __nv_bfloat16* __restrict__ lo, int n)
{
    const int i = blockIdx.x * blockDim.x + threadIdx.x;
    if (i < n) {
        const float v = in[i];
        const __nv_bfloat16 h = __float2bfloat16(v);
        hi[i] = h;
        lo[i] = __float2bfloat16(v - __bfloat162float(h));
    }
}

// ---------------------------------------------------------------------------
// Row softmax over L=4096 on k rows (rows 512..1023 of each batch's qkv)
// ---------------------------------------------------------------------------
__global__ __launch_bounds__(256) void softmax_kernel()
{
    const int row = blockIdx.x;
    const int b = row >> 9;
    const int r = row & 511;
    float* p = g_qkv + (long long)b * QKV_ROWS * LDIM + (long long)(HID + r) * LDIM;

    const int tid = threadIdx.x;
    __shared__ float red[256];

    float4 v[4];
#pragma unroll
    for (int i = 0; i < 4; i++)
        v[i] = *(const float4*)(p + i * 1024 + tid * 4);

    float vmax = -1e30f;
#pragma unroll
    for (int i = 0; i < 4; i++)
        vmax = fmaxf(vmax, fmaxf(fmaxf(v[i].x, v[i].y), fmaxf(v[i].z, v[i].w)));
    red[tid] = vmax;
    __syncthreads();
    for (int s = 128; s > 0; s >>= 1) {
        if (tid < s) red[tid] = fmaxf(red[tid], red[tid + s]);
        __syncthreads();
    }
    vmax = red[0];
    __syncthreads();

    float lsum = 0.0f;
#pragma unroll
    for (int i = 0; i < 4; i++) {
        v[i].x = expf(v[i].x - vmax); lsum += v[i].x;
        v[i].y = expf(v[i].y - vmax); lsum += v[i].y;
        v[i].z = expf(v[i].z - vmax); lsum += v[i].z;
        v[i].w = expf(v[i].w - vmax); lsum += v[i].w;
    }
    red[tid] = lsum;
    __syncthreads();
    for (int s = 128; s > 0; s >>= 1) {
        if (tid < s) red[tid] += red[tid + s];
        __syncthreads();
    }
    const float inv = 1.0f / red[0];

#pragma unroll
    for (int i = 0; i < 4; i++) {
        v[i].x *= inv; v[i].y *= inv; v[i].z *= inv; v[i].w *= inv;
        *(float4*)(p + i * 1024 + tid * 4) = v[i];
    }
}

// ---------------------------------------------------------------------------
// Context partials + reduce + fold (fp32)
// ---------------------------------------------------------------------------
__global__ __launch_bounds__(256) void context_partial_kernel()
{
    const int split = blockIdx.x;
    const int bh = blockIdx.y;
    const int b = bh >> 3, h = bh & 7;

    const float* kbase = g_qkv + (long long)b * QKV_ROWS * LDIM + (long long)(HID + h * DHEAD) * LDIM;
    const float* vbase = g_qkv + (long long)b * QKV_ROWS * LDIM + (long long)(2 * HID + h * DHEAD) * LDIM;

    __shared__ float Ks[64][65];
    __shared__ float Vs[64][65];

    const int tid = threadIdx.x;
    const int td = (tid >> 4) * 4;
    const int te = (tid & 15) * 4;

    float acc[4][4];
#pragma unroll
    for (int i = 0; i < 4; i++)
#pragma unroll
        for (int j = 0; j < 4; j++) acc[i][j] = 0.0f;

    const int chunk = LDIM / CSPLIT;
    for (int sub = 0; sub < chunk / 64; sub++) {
        const int n0 = split * chunk + sub * 64;
        for (int i = tid; i < 1024; i += 256) {
            const int r = i >> 4, c = (i & 15) * 4;
            float4 kv = *(const float4*)(kbase + (long long)r * LDIM + n0 + c);
            Ks[r][c] = kv.x; Ks[r][c + 1] = kv.y; Ks[r][c + 2] = kv.z; Ks[r][c + 3] = kv.w;
            float4 vv = *(const float4*)(vbase + (long long)r * LDIM + n0 + c);
            Vs[r][c] = vv.x; Vs[r][c + 1] = vv.y; Vs[r][c + 2] = vv.z; Vs[r][c + 3] = vv.w;
        }
        __syncthreads();

#pragma unroll 8
        for (int n = 0; n < 64; n++) {
            float kr[4], vr[4];
#pragma unroll
            for (int i = 0; i < 4; i++) kr[i] = Ks[td + i][n];
#pragma unroll
            for (int j = 0; j < 4; j++) vr[j] = Vs[te + j][n];
#pragma unroll
            for (int i = 0; i < 4; i++)
#pragma unroll
                for (int j = 0; j < 4; j++)
                    acc[i][j] = fmaf(kr[i], vr[j], acc[i][j]);
        }
        __syncthreads();
    }

    float* pout = g_part + ((long long)split * 64 + bh) * (DHEAD * DHEAD);
#pragma unroll
    for (int i = 0; i < 4; i++)
#pragma unroll
        for (int j = 0; j < 4; j++)
            pout[(td + i) * DHEAD + (te + j)] = acc[i][j];
}

__global__ __launch_bounds__(256) void reduce_ctx_kernel()
{
    const int i = blockIdx.x * blockDim.x + threadIdx.x;
    const int total = BATCH * HEADS * DHEAD * DHEAD;
    if (i < total) {
        float s = 0.0f;
#pragma unroll
        for (int sp = 0; sp < CSPLIT; sp++)
            s += g_part[(long long)sp * total + i];
        g_ctx[i] = s;
    }
}

__global__ __launch_bounds__(256) void fold_kernel(const float* __restrict__ w_out)
{
    const int oc = blockIdx.x;
    const int bh = blockIdx.y;
    const int b = bh >> 3, h = bh & 7;

    __shared__ float cs[64][65];
    __shared__ float ws[64][65];

    const int tid = threadIdx.x;
    for (int i = tid; i < 4096; i += 256) {
        const int d = i >> 6, e = i & 63;
        cs[d][e] = g_ctx[((long long)bh * 64 + d) * 64 + e];
    }
    for (int i = tid; i < 4096; i += 256) {
        const int r = i >> 6, e = i & 63;
        ws[r][e] = w_out[(long long)(oc * 64 + r) * CDIM + h * 64 + e];
    }
    __syncthreads();

    const int d = tid & 63;
    const int r0 = (tid >> 6) * 16;
    for (int rr = 0; rr < 16; rr++) {
        float s = 0.0f;
#pragma unroll 8
        for (int e = 0; e < 64; e++)
            s = fmaf(ws[r0 + rr][e], cs[d][e], s);
        g_M[((long long)b * HID + oc * 64 + r0 + rr) * HID + h * 64 + d] = s;
    }
}

// ---------------------------------------------------------------------------
extern "C" void kernel_launch(void* const* d_in, const int* in_sizes, int n_in,
                              void* d_out, int out_size)
{
    const float* x     = (const float*)d_in[0];   // [8, 512, 4096]
    const float* w_qkv = (const float*)d_in[1];   // [1536, 512]
    const float* w_out = (const float*)d_in[2];   // [512, 512]
    const float* b_out = (const float*)d_in[3];   // [512]
    float* out = (float*)d_out;                   // [8, 512, 4096]

    float *p_qkv, *p_M;
    __nv_bfloat16 *p_xthi, *p_xtlo, *p_qthi, *p_qtlo, *p_whi, *p_wlo, *p_Mhi, *p_Mlo;
    cudaGetSymbolAddress((void**)&p_qkv, g_qkv);
    cudaGetSymbolAddress((void**)&p_M, g_M);
    cudaGetSymbolAddress((void**)&p_xthi, g_xt_hi);
    cudaGetSymbolAddress((void**)&p_xtlo, g_xt_lo);
    cudaGetSymbolAddress((void**)&p_qthi, g_qt_hi);
    cudaGetSymbolAddress((void**)&p_qtlo, g_qt_lo);
    cudaGetSymbolAddress((void**)&p_whi, g_w_hi);
    cudaGetSymbolAddress((void**)&p_wlo, g_w_lo);
    cudaGetSymbolAddress((void**)&p_Mhi, g_M_hi);
    cudaGetSymbolAddress((void**)&p_Mlo, g_M_lo);

    int nsm = 148;
    cudaDeviceGetAttribute(&nsm, cudaDevAttrMultiProcessorCount, 0);

    cudaFuncSetAttribute(mma_gemm_persistent,
                         cudaFuncAttributeMaxDynamicSharedMemorySize, GEMM_SMEM);

    // 0) split-convert W; transpose+split X
    convert_split_kernel<<<(QKV_ROWS * CDIM + 255) / 256, 256>>>(w_qkv, p_whi, p_wlo, QKV_ROWS * CDIM);
    transpose_convert_kernel<<<dim3(LDIM / 32, CDIM / 32, BATCH), 256>>>(
        x, p_xthi, p_xtlo, CDIM, LDIM,
        (long long)CDIM * LDIM, (long long)LDIM * CDIM);

    // 1) qkv = W @ x  (persistent split-bf16 HMMA)
    mma_gemm_persistent<<<nsm, 256, GEMM_SMEM>>>(
        p_whi, p_wlo, p_xthi, p_xtlo, p_qkv,
        QKV_ROWS / 128, LDIM / 128, BATCH, LDIM, CDIM,
        0LL, (long long)LDIM * CDIM, (long long)QKV_ROWS * LDIM, nullptr);

    // 2) transpose+split q (rows 0..511 of qkv per batch)
    transpose_convert_kernel<<<dim3(LDIM / 32, HID / 32, BATCH), 256>>>(
        p_qkv, p_qthi, p_qtlo, HID, LDIM,
        (long long)QKV_ROWS * LDIM, (long long)LDIM * HID);

    // 3) softmax over L on k rows
    softmax_kernel<<<BATCH * HID, 256>>>();

    // 4) context partials + deterministic reduce
    context_partial_kernel<<<dim3(CSPLIT, BATCH * HEADS), 256>>>();
    {
        const int total = BATCH * HEADS * DHEAD * DHEAD;
        reduce_ctx_kernel<<<(total + 255) / 256, 256>>>();
    }

    // 5) fold w_out with context -> per-batch M; split-convert M
    fold_kernel<<<dim3(8, BATCH * HEADS), 256>>>(w_out);
    convert_split_kernel<<<(BATCH * HID * HID + 255) / 256, 256>>>(p_M, p_Mhi, p_Mlo, BATCH * HID * HID);

    // 6) out = M @ q + b_out  (persistent split-bf16 HMMA)
    mma_gemm_persistent<<<nsm, 256, GEMM_SMEM>>>(
        p_Mhi, p_Mlo, p_qthi, p_qtlo, out,
        HID / 128, LDIM / 128, BATCH, LDIM, HID,
        (long long)HID * HID, (long long)LDIM * HID, (long long)HID * LDIM, b_out);
}

// round 9
// speedup vs baseline: 2.9856x; 1.2020x over previous
#include <cuda_runtime.h>
#include <cuda_bf16.h>
#include <cstdint>

// Problem constants
#define BATCH 8
#define CDIM 512
#define LDIM 4096
#define HEADS 8
#define DHEAD 64
#define HID 512            // HEADS*DHEAD
#define QKV_ROWS 1536      // 3*HID
#define KV_ROWS 1024       // k,v only
#define CSPLIT 32          // n-splits for context partials

// ---------------------------------------------------------------------------
// Scratch (device globals; no allocation allowed)
// ---------------------------------------------------------------------------
__device__ float g_kv[(size_t)BATCH * KV_ROWS * LDIM];          // k rows 0..511, v rows 512..1023
__device__ __nv_bfloat16 g_xt_hi[(size_t)BATCH * LDIM * CDIM];  // x^T
__device__ __nv_bfloat16 g_xt_lo[(size_t)BATCH * LDIM * CDIM];
__device__ __nv_bfloat16 g_w_hi[(size_t)QKV_ROWS * CDIM];
__device__ __nv_bfloat16 g_w_lo[(size_t)QKV_ROWS * CDIM];
__device__ __nv_bfloat16 g_wqT_hi[(size_t)CDIM * HID];          // Wq^T [c][hd]
__device__ __nv_bfloat16 g_wqT_lo[(size_t)CDIM * HID];
__device__ float g_part[(size_t)CSPLIT * BATCH * HEADS * DHEAD * DHEAD];
__device__ float g_ctx[(size_t)BATCH * HEADS * DHEAD * DHEAD];
__device__ float g_M[(size_t)BATCH * HID * HID];
__device__ __nv_bfloat16 g_M_hi[(size_t)BATCH * HID * HID];
__device__ __nv_bfloat16 g_M_lo[(size_t)BATCH * HID * HID];
__device__ __nv_bfloat16 g_N_hi[(size_t)BATCH * HID * HID];     // N = M @ Wq
__device__ __nv_bfloat16 g_N_lo[(size_t)BATCH * HID * HID];

// ---------------------------------------------------------------------------
// PTX helpers (baseline sm_103 — mma.sync bf16 only)
// ---------------------------------------------------------------------------
__device__ __forceinline__ uint32_t smem_to_u32(const void* smem_ptr) {
    uint32_t addr;
    asm("{ .reg .u64 tmp; cvta.to.shared.u64 tmp, %1; cvt.u32.u64 %0, tmp; }"
        : "=r"(addr) : "l"(smem_ptr));
    return addr;
}

#define SMEM_SWIZZLE_128B(byte_offset) \
    ((uint32_t)(byte_offset) ^ ((((uint32_t)(byte_offset)) >> 3) & 0x70u))

__device__ __forceinline__ void cp_async16(uint32_t dst, const void* src) {
    asm volatile("cp.async.cg.shared.global [%0], [%1], 16;"
                 :: "r"(dst), "l"(src) : "memory");
}
#define CP_ASYNC_COMMIT() asm volatile("cp.async.commit_group;" ::: "memory")
#define CP_ASYNC_WAIT(n)  asm volatile("cp.async.wait_group %0;" :: "n"(n) : "memory")

__device__ __forceinline__ void ldsm4(uint32_t* r, uint32_t addr) {
    asm volatile("ldmatrix.sync.aligned.m8n8.x4.shared.b16 {%0,%1,%2,%3}, [%4];"
                 : "=r"(r[0]), "=r"(r[1]), "=r"(r[2]), "=r"(r[3]) : "r"(addr));
}

__device__ __forceinline__ void mma_bf16(float* c, const uint32_t* a, const uint32_t* b) {
    asm volatile(
        "mma.sync.aligned.m16n8k16.row.col.f32.bf16.bf16.f32 "
        "{%0,%1,%2,%3}, {%4,%5,%6,%7}, {%8,%9}, {%0,%1,%2,%3};"
        : "+f"(c[0]), "+f"(c[1]), "+f"(c[2]), "+f"(c[3])
        : "r"(a[0]), "r"(a[1]), "r"(a[2]), "r"(a[3]), "r"(b[0]), "r"(b[1]));
}

// ---------------------------------------------------------------------------
// Persistent split-bf16 HMMA GEMM: C[M,N] = A[M,K] @ B[N,K]^T (+row bias)
// K = 512 (8 chunks of BK=64). Tile 128x128, 256 threads, warp tile 64x32.
// 3-stage cp.async pipeline running continuously across tiles.
// If Ohi != null: write hi/lo split-bf16 output instead of fp32 C.
// ---------------------------------------------------------------------------
#define STAGE_BYTES 65536
#define OFF_AHI 0
#define OFF_ALO 16384
#define OFF_BHI 32768
#define OFF_BLO 49152
#define GEMM_SMEM (3 * STAGE_BYTES)
#define CHUNKS_PER_TILE 8    // K=512 / BK=64

__global__ __launch_bounds__(256, 1)
void mma_gemm_persistent(const __nv_bfloat16* __restrict__ Ahi,
                         const __nv_bfloat16* __restrict__ Alo,
                         const __nv_bfloat16* __restrict__ Bhi,
                         const __nv_bfloat16* __restrict__ Blo,
                         float* __restrict__ C,
                         int ntm, int ntn, int nb, int N, int K,
                         long long sA, long long sB, long long sC,
                         const float* __restrict__ bias,
                         __nv_bfloat16* __restrict__ Ohi,
                         __nv_bfloat16* __restrict__ Olo)
{
    extern __shared__ char smem[];
    const uint32_t sbase = smem_to_u32(smem);

    const int tid = threadIdx.x;
    const int wid = tid >> 5;
    const int lane = tid & 31;
    const int warp_m = wid >> 2;       // 0..1 (64 rows)
    const int warp_n = wid & 3;        // 0..3 (32 cols)

    const int ntiles = ntm * ntn * nb;
    const int my_ntiles = (ntiles - (int)blockIdx.x + (int)gridDim.x - 1) / (int)gridDim.x;
    if (my_ntiles <= 0) return;
    const int my_nchunks = my_ntiles * CHUNKS_PER_TILE;

    auto load_chunk = [&](int k) {
        const int t = k >> 3;
        const int tile_lin = (int)blockIdx.x + t * (int)gridDim.x;
        if (tile_lin >= ntiles) { CP_ASYNC_COMMIT(); return; }
        const int nx = tile_lin % ntn;
        const int rest = tile_lin / ntn;
        const int my = rest % ntm;
        const int b = rest / ntm;
        const int bm = my << 7;
        const int bn = nx << 7;
        const int k0 = (k & 7) << 6;
        const __nv_bfloat16* pAhi = Ahi + (long long)b * sA;
        const __nv_bfloat16* pAlo = Alo + (long long)b * sA;
        const __nv_bfloat16* pBhi = Bhi + (long long)b * sB;
        const __nv_bfloat16* pBlo = Blo + (long long)b * sB;
        const uint32_t sb = sbase + (uint32_t)(k % 3) * STAGE_BYTES;
#pragma unroll
        for (int it = 0; it < 4; it++) {
            const int g = it * 256 + tid;
            const int row = g >> 3;
            const int gr = g & 7;
            const uint32_t sw = SMEM_SWIZZLE_128B(row * 128 + gr * 16);
            const long long aoff = (long long)(bm + row) * K + k0 + gr * 8;
            const long long boff = (long long)(bn + row) * K + k0 + gr * 8;
            cp_async16(sb + OFF_AHI + sw, pAhi + aoff);
            cp_async16(sb + OFF_ALO + sw, pAlo + aoff);
            cp_async16(sb + OFF_BHI + sw, pBhi + boff);
            cp_async16(sb + OFF_BLO + sw, pBlo + boff);
        }
        CP_ASYNC_COMMIT();
    };

    float acc[4][4][4];
#pragma unroll
    for (int i = 0; i < 4; i++)
#pragma unroll
        for (int j = 0; j < 4; j++)
#pragma unroll
            for (int r = 0; r < 4; r++) acc[i][j][r] = 0.0f;

    load_chunk(0);
    load_chunk(1);

    for (int k = 0; k < my_nchunks; k++) {
        CP_ASYNC_WAIT(1);
        __syncthreads();

        const uint32_t sb = sbase + (uint32_t)(k % 3) * STAGE_BYTES;
#pragma unroll
        for (int ks = 0; ks < 4; ks++) {
            uint32_t bhi[8], blo[8];
#pragma unroll
            for (int p = 0; p < 2; p++) {
                const int r = warp_n * 32 + p * 16 + ((lane >> 4) & 1) * 8 + (lane & 7);
                const int cb = ks * 32 + ((lane >> 3) & 1) * 16;
                const uint32_t adr = sb + OFF_BHI + SMEM_SWIZZLE_128B(r * 128 + cb);
                ldsm4(bhi + p * 4, adr);
                ldsm4(blo + p * 4, adr + (OFF_BLO - OFF_BHI));
            }
#pragma unroll
            for (int i = 0; i < 4; i++) {
                const int r = warp_m * 64 + i * 16 + ((lane >> 3) & 1) * 8 + (lane & 7);
                const int cb = ks * 32 + ((lane >> 4) & 1) * 16;
                const uint32_t adr = sb + OFF_AHI + SMEM_SWIZZLE_128B(r * 128 + cb);
                uint32_t ahi[4], alo[4];
                ldsm4(ahi, adr);
                ldsm4(alo, adr + (OFF_ALO - OFF_AHI));
#pragma unroll
                for (int j = 0; j < 4; j++) {
                    const uint32_t* bh = bhi + (j >> 1) * 4 + (j & 1) * 2;
                    const uint32_t* bl = blo + (j >> 1) * 4 + (j & 1) * 2;
                    mma_bf16(acc[i][j], ahi, bh);
                    mma_bf16(acc[i][j], ahi, bl);
                    mma_bf16(acc[i][j], alo, bh);
                }
            }
        }

        load_chunk(k + 2);   // 3-stage rotation: no WAR hazard

        if ((k & 7) == 7) {
            const int t = k >> 3;
            const int tile_lin = (int)blockIdx.x + t * (int)gridDim.x;
            const int nx = tile_lin % ntn;
            const int rest = tile_lin / ntn;
            const int my = rest % ntm;
            const int b = rest / ntm;
            const int bm = my << 7;
            const int bn = nx << 7;
            if (Ohi == nullptr) {
                float* pC = C + (long long)b * sC;
#pragma unroll
                for (int i = 0; i < 4; i++) {
                    const int m0 = bm + warp_m * 64 + i * 16 + (lane >> 2);
                    const float bv0 = bias ? bias[m0] : 0.0f;
                    const float bv1 = bias ? bias[m0 + 8] : 0.0f;
#pragma unroll
                    for (int j = 0; j < 4; j++) {
                        const int n0 = bn + warp_n * 32 + j * 8 + (lane & 3) * 2;
                        float2 v0, v1;
                        v0.x = acc[i][j][0] + bv0;  v0.y = acc[i][j][1] + bv0;
                        v1.x = acc[i][j][2] + bv1;  v1.y = acc[i][j][3] + bv1;
                        *(float2*)(pC + (long long)m0 * N + n0) = v0;
                        *(float2*)(pC + (long long)(m0 + 8) * N + n0) = v1;
                        acc[i][j][0] = 0.0f; acc[i][j][1] = 0.0f;
                        acc[i][j][2] = 0.0f; acc[i][j][3] = 0.0f;
                    }
                }
            } else {
                // split-bf16 output (no bias path needed)
                __nv_bfloat16* pH = Ohi + (long long)b * sC;
                __nv_bfloat16* pL = Olo + (long long)b * sC;
#pragma unroll
                for (int i = 0; i < 4; i++) {
                    const int m0 = bm + warp_m * 64 + i * 16 + (lane >> 2);
#pragma unroll
                    for (int j = 0; j < 4; j++) {
                        const int n0 = bn + warp_n * 32 + j * 8 + (lane & 3) * 2;
#pragma unroll
                        for (int r = 0; r < 4; r++) {
                            const int mm = m0 + (r >> 1) * 8;
                            const int nn = n0 + (r & 1);
                            const float v = acc[i][j][r];
                            const __nv_bfloat16 hi = __float2bfloat16(v);
                            pH[(long long)mm * N + nn] = hi;
                            pL[(long long)mm * N + nn] = __float2bfloat16(v - __bfloat162float(hi));
                            acc[i][j][r] = 0.0f;
                        }
                    }
                }
            }
        }
    }
}

// ---------------------------------------------------------------------------
// Transpose + split-convert: in fp32 [R, L] -> out_hi/out_lo bf16 [L, R]
// ---------------------------------------------------------------------------
__global__ __launch_bounds__(256) void transpose_convert_kernel(
    const float* __restrict__ in,
    __nv_bfloat16* __restrict__ out_hi, __nv_bfloat16* __restrict__ out_lo,
    int R, int L, long long inStride, long long outStride)
{
    const int b = blockIdx.z;
    in += (long long)b * inStride;
    out_hi += (long long)b * outStride;
    out_lo += (long long)b * outStride;

    __shared__ float t[32][33];
    const int r0 = blockIdx.y * 32;
    const int c0 = blockIdx.x * 32;
    const int tx = threadIdx.x & 31;
    const int ty = threadIdx.x >> 5;

#pragma unroll
    for (int i = 0; i < 4; i++)
        t[ty + i * 8][tx] = in[(long long)(r0 + ty + i * 8) * L + c0 + tx];
    __syncthreads();
#pragma unroll
    for (int i = 0; i < 4; i++) {
        const float v = t[tx][ty + i * 8];
        const __nv_bfloat16 hi = __float2bfloat16(v);
        const float lo = v - __bfloat162float(hi);
        const long long o = (long long)(c0 + ty + i * 8) * R + r0 + tx;
        out_hi[o] = hi;
        out_lo[o] = __float2bfloat16(lo);
    }
}

// Plain split-convert
__global__ __launch_bounds__(256) void convert_split_kernel(
    const float* __restrict__ in,
    __nv_bfloat16* __restrict__ hi, __nv_bfloat16* __restrict__ lo, int n)
{
    const int i = blockIdx.x * blockDim.x + threadIdx.x;
    if (i < n) {
        const float v = in[i];
        const __nv_bfloat16 h = __float2bfloat16(v);
        hi[i] = h;
        lo[i] = __float2bfloat16(v - __bfloat162float(h));
    }
}

// ---------------------------------------------------------------------------
// Row softmax over L=4096 on k rows (rows 0..511 of g_kv per batch)
// ---------------------------------------------------------------------------
__global__ __launch_bounds__(256) void softmax_kernel()
{
    const int row = blockIdx.x;           // 0..BATCH*512-1
    const int b = row >> 9;
    const int r = row & 511;
    float* p = g_kv + (long long)b * KV_ROWS * LDIM + (long long)r * LDIM;

    const int tid = threadIdx.x;
    __shared__ float red[256];

    float4 v[4];
#pragma unroll
    for (int i = 0; i < 4; i++)
        v[i] = *(const float4*)(p + i * 1024 + tid * 4);

    float vmax = -1e30f;
#pragma unroll
    for (int i = 0; i < 4; i++)
        vmax = fmaxf(vmax, fmaxf(fmaxf(v[i].x, v[i].y), fmaxf(v[i].z, v[i].w)));
    red[tid] = vmax;
    __syncthreads();
    for (int s = 128; s > 0; s >>= 1) {
        if (tid < s) red[tid] = fmaxf(red[tid], red[tid + s]);
        __syncthreads();
    }
    vmax = red[0];
    __syncthreads();

    float lsum = 0.0f;
#pragma unroll
    for (int i = 0; i < 4; i++) {
        v[i].x = expf(v[i].x - vmax); lsum += v[i].x;
        v[i].y = expf(v[i].y - vmax); lsum += v[i].y;
        v[i].z = expf(v[i].z - vmax); lsum += v[i].z;
        v[i].w = expf(v[i].w - vmax); lsum += v[i].w;
    }
    red[tid] = lsum;
    __syncthreads();
    for (int s = 128; s > 0; s >>= 1) {
        if (tid < s) red[tid] += red[tid + s];
        __syncthreads();
    }
    const float inv = 1.0f / red[0];

#pragma unroll
    for (int i = 0; i < 4; i++) {
        v[i].x *= inv; v[i].y *= inv; v[i].z *= inv; v[i].w *= inv;
        *(float4*)(p + i * 1024 + tid * 4) = v[i];
    }
}

// ---------------------------------------------------------------------------
// Context partials + reduce + fold (fp32)
// ---------------------------------------------------------------------------
__global__ __launch_bounds__(256) void context_partial_kernel()
{
    const int split = blockIdx.x;
    const int bh = blockIdx.y;
    const int b = bh >> 3, h = bh & 7;

    const float* kbase = g_kv + (long long)b * KV_ROWS * LDIM + (long long)(h * DHEAD) * LDIM;
    const float* vbase = g_kv + (long long)b * KV_ROWS * LDIM + (long long)(HID + h * DHEAD) * LDIM;

    __shared__ float Ks[64][65];
    __shared__ float Vs[64][65];

    const int tid = threadIdx.x;
    const int td = (tid >> 4) * 4;
    const int te = (tid & 15) * 4;

    float acc[4][4];
#pragma unroll
    for (int i = 0; i < 4; i++)
#pragma unroll
        for (int j = 0; j < 4; j++) acc[i][j] = 0.0f;

    const int chunk = LDIM / CSPLIT;
    for (int sub = 0; sub < chunk / 64; sub++) {
        const int n0 = split * chunk + sub * 64;
        for (int i = tid; i < 1024; i += 256) {
            const int r = i >> 4, c = (i & 15) * 4;
            float4 kv = *(const float4*)(kbase + (long long)r * LDIM + n0 + c);
            Ks[r][c] = kv.x; Ks[r][c + 1] = kv.y; Ks[r][c + 2] = kv.z; Ks[r][c + 3] = kv.w;
            float4 vv = *(const float4*)(vbase + (long long)r * LDIM + n0 + c);
            Vs[r][c] = vv.x; Vs[r][c + 1] = vv.y; Vs[r][c + 2] = vv.z; Vs[r][c + 3] = vv.w;
        }
        __syncthreads();

#pragma unroll 8
        for (int n = 0; n < 64; n++) {
            float kr[4], vr[4];
#pragma unroll
            for (int i = 0; i < 4; i++) kr[i] = Ks[td + i][n];
#pragma unroll
            for (int j = 0; j < 4; j++) vr[j] = Vs[te + j][n];
#pragma unroll
            for (int i = 0; i < 4; i++)
#pragma unroll
                for (int j = 0; j < 4; j++)
                    acc[i][j] = fmaf(kr[i], vr[j], acc[i][j]);
        }
        __syncthreads();
    }

    float* pout = g_part + ((long long)split * 64 + bh) * (DHEAD * DHEAD);
#pragma unroll
    for (int i = 0; i < 4; i++)
#pragma unroll
        for (int j = 0; j < 4; j++)
            pout[(td + i) * DHEAD + (te + j)] = acc[i][j];
}

__global__ __launch_bounds__(256) void reduce_ctx_kernel()
{
    const int i = blockIdx.x * blockDim.x + threadIdx.x;
    const int total = BATCH * HEADS * DHEAD * DHEAD;
    if (i < total) {
        float s = 0.0f;
#pragma unroll
        for (int sp = 0; sp < CSPLIT; sp++)
            s += g_part[(long long)sp * total + i];
        g_ctx[i] = s;
    }
}

__global__ __launch_bounds__(256) void fold_kernel(const float* __restrict__ w_out)
{
    const int oc = blockIdx.x;
    const int bh = blockIdx.y;
    const int b = bh >> 3, h = bh & 7;

    __shared__ float cs[64][65];
    __shared__ float ws[64][65];

    const int tid = threadIdx.x;
    for (int i = tid; i < 4096; i += 256) {
        const int d = i >> 6, e = i & 63;
        cs[d][e] = g_ctx[((long long)bh * 64 + d) * 64 + e];
    }
    for (int i = tid; i < 4096; i += 256) {
        const int r = i >> 6, e = i & 63;
        ws[r][e] = w_out[(long long)(oc * 64 + r) * CDIM + h * 64 + e];
    }
    __syncthreads();

    const int d = tid & 63;
    const int r0 = (tid >> 6) * 16;
    for (int rr = 0; rr < 16; rr++) {
        float s = 0.0f;
#pragma unroll 8
        for (int e = 0; e < 64; e++)
            s = fmaf(ws[r0 + rr][e], cs[d][e], s);
        g_M[((long long)b * HID + oc * 64 + r0 + rr) * HID + h * 64 + d] = s;
    }
}

// ---------------------------------------------------------------------------
extern "C" void kernel_launch(void* const* d_in, const int* in_sizes, int n_in,
                              void* d_out, int out_size)
{
    const float* x     = (const float*)d_in[0];   // [8, 512, 4096]
    const float* w_qkv = (const float*)d_in[1];   // [1536, 512]
    const float* w_out = (const float*)d_in[2];   // [512, 512]
    const float* b_out = (const float*)d_in[3];   // [512]
    float* out = (float*)d_out;                   // [8, 512, 4096]

    float *p_kv, *p_M;
    __nv_bfloat16 *p_xthi, *p_xtlo, *p_whi, *p_wlo, *p_wqThi, *p_wqTlo;
    __nv_bfloat16 *p_Mhi, *p_Mlo, *p_Nhi, *p_Nlo;
    cudaGetSymbolAddress((void**)&p_kv, g_kv);
    cudaGetSymbolAddress((void**)&p_M, g_M);
    cudaGetSymbolAddress((void**)&p_xthi, g_xt_hi);
    cudaGetSymbolAddress((void**)&p_xtlo, g_xt_lo);
    cudaGetSymbolAddress((void**)&p_whi, g_w_hi);
    cudaGetSymbolAddress((void**)&p_wlo, g_w_lo);
    cudaGetSymbolAddress((void**)&p_wqThi, g_wqT_hi);
    cudaGetSymbolAddress((void**)&p_wqTlo, g_wqT_lo);
    cudaGetSymbolAddress((void**)&p_Mhi, g_M_hi);
    cudaGetSymbolAddress((void**)&p_Mlo, g_M_lo);
    cudaGetSymbolAddress((void**)&p_Nhi, g_N_hi);
    cudaGetSymbolAddress((void**)&p_Nlo, g_N_lo);

    int nsm = 148;
    cudaDeviceGetAttribute(&nsm, cudaDevAttrMultiProcessorCount, 0);

    cudaFuncSetAttribute(mma_gemm_persistent,
                         cudaFuncAttributeMaxDynamicSharedMemorySize, GEMM_SMEM);

    // 0) split-convert W (all rows); transpose+split x; transpose+split Wq
    convert_split_kernel<<<(QKV_ROWS * CDIM + 255) / 256, 256>>>(w_qkv, p_whi, p_wlo, QKV_ROWS * CDIM);
    transpose_convert_kernel<<<dim3(LDIM / 32, CDIM / 32, BATCH), 256>>>(
        x, p_xthi, p_xtlo, CDIM, LDIM,
        (long long)CDIM * LDIM, (long long)LDIM * CDIM);
    transpose_convert_kernel<<<dim3(CDIM / 32, HID / 32, 1), 256>>>(
        w_qkv, p_wqThi, p_wqTlo, HID, CDIM, 0LL, 0LL);

    // 1) kv = W_kv @ x  (rows 512..1535 of W)
    mma_gemm_persistent<<<nsm, 256, GEMM_SMEM>>>(
        p_whi + (size_t)HID * CDIM, p_wlo + (size_t)HID * CDIM,
        p_xthi, p_xtlo, p_kv,
        KV_ROWS / 128, LDIM / 128, BATCH, LDIM, CDIM,
        0LL, (long long)LDIM * CDIM, (long long)KV_ROWS * LDIM, nullptr,
        nullptr, nullptr);

    // 2) softmax over L on k rows
    softmax_kernel<<<BATCH * HID, 256>>>();

    // 3) context partials + deterministic reduce
    context_partial_kernel<<<dim3(CSPLIT, BATCH * HEADS), 256>>>();
    {
        const int total = BATCH * HEADS * DHEAD * DHEAD;
        reduce_ctx_kernel<<<(total + 255) / 256, 256>>>();
    }

    // 4) fold w_out with context -> M; split M
    fold_kernel<<<dim3(8, BATCH * HEADS), 256>>>(w_out);
    convert_split_kernel<<<(BATCH * HID * HID + 255) / 256, 256>>>(p_M, p_Mhi, p_Mlo, BATCH * HID * HID);

    // 5) N = M @ Wq  (split-bf16 in, split-bf16 out)
    mma_gemm_persistent<<<nsm, 256, GEMM_SMEM>>>(
        p_Mhi, p_Mlo, p_wqThi, p_wqTlo, nullptr,
        HID / 128, HID / 128, BATCH, HID, CDIM,
        (long long)HID * HID, 0LL, (long long)HID * HID, nullptr,
        p_Nhi, p_Nlo);

    // 6) out = N @ x + b_out
    mma_gemm_persistent<<<nsm, 256, GEMM_SMEM>>>(
        p_Nhi, p_Nlo, p_xthi, p_xtlo, out,
        HID / 128, LDIM / 128, BATCH, LDIM, CDIM,
        (long long)HID * HID, (long long)LDIM * CDIM, (long long)HID * LDIM, b_out,
        nullptr, nullptr);
}

// round 10
// speedup vs baseline: 3.0207x; 1.0117x over previous
#include <cuda_runtime.h>
#include <cuda_bf16.h>
#include <cstdint>

// Problem constants
#define BATCH 8
#define CDIM 512
#define LDIM 4096
#define HEADS 8
#define DHEAD 64
#define HID 512            // HEADS*DHEAD
#define QKV_ROWS 1536      // 3*HID
#define KV_ROWS 1024       // k,v only
#define CSPLIT 32          // n-splits for context partials

// ---------------------------------------------------------------------------
// Scratch (device globals; no allocation allowed)
// ---------------------------------------------------------------------------
__device__ float g_kv[(size_t)BATCH * KV_ROWS * LDIM];          // k rows 0..511, v rows 512..1023
__device__ __nv_bfloat16 g_xt_hi[(size_t)BATCH * LDIM * CDIM];  // x^T
__device__ __nv_bfloat16 g_xt_lo[(size_t)BATCH * LDIM * CDIM];
__device__ __nv_bfloat16 g_w_hi[(size_t)QKV_ROWS * CDIM];
__device__ __nv_bfloat16 g_w_lo[(size_t)QKV_ROWS * CDIM];
__device__ __nv_bfloat16 g_wqT_hi[(size_t)CDIM * HID];          // Wq^T [c][hd]
__device__ __nv_bfloat16 g_wqT_lo[(size_t)CDIM * HID];
__device__ float g_part[(size_t)CSPLIT * BATCH * HEADS * DHEAD * DHEAD];
__device__ float g_ctx[(size_t)BATCH * HEADS * DHEAD * DHEAD];
__device__ __nv_bfloat16 g_M_hi[(size_t)BATCH * HID * HID];
__device__ __nv_bfloat16 g_M_lo[(size_t)BATCH * HID * HID];
__device__ __nv_bfloat16 g_N_hi[(size_t)BATCH * HID * HID];     // N = M @ Wq
__device__ __nv_bfloat16 g_N_lo[(size_t)BATCH * HID * HID];

// ---------------------------------------------------------------------------
// PTX helpers (baseline sm_103 — mma.sync bf16 only)
// ---------------------------------------------------------------------------
__device__ __forceinline__ uint32_t smem_to_u32(const void* smem_ptr) {
    uint32_t addr;
    asm("{ .reg .u64 tmp; cvta.to.shared.u64 tmp, %1; cvt.u32.u64 %0, tmp; }"
        : "=r"(addr) : "l"(smem_ptr));
    return addr;
}

#define SMEM_SWIZZLE_128B(byte_offset) \
    ((uint32_t)(byte_offset) ^ ((((uint32_t)(byte_offset)) >> 3) & 0x70u))

__device__ __forceinline__ void cp_async16(uint32_t dst, const void* src) {
    asm volatile("cp.async.cg.shared.global [%0], [%1], 16;"
                 :: "r"(dst), "l"(src) : "memory");
}
#define CP_ASYNC_COMMIT() asm volatile("cp.async.commit_group;" ::: "memory")
#define CP_ASYNC_WAIT(n)  asm volatile("cp.async.wait_group %0;" :: "n"(n) : "memory")

__device__ __forceinline__ void ldsm4(uint32_t* r, uint32_t addr) {
    asm volatile("ldmatrix.sync.aligned.m8n8.x4.shared.b16 {%0,%1,%2,%3}, [%4];"
                 : "=r"(r[0]), "=r"(r[1]), "=r"(r[2]), "=r"(r[3]) : "r"(addr));
}

__device__ __forceinline__ void mma_bf16(float* c, const uint32_t* a, const uint32_t* b) {
    asm volatile(
        "mma.sync.aligned.m16n8k16.row.col.f32.bf16.bf16.f32 "
        "{%0,%1,%2,%3}, {%4,%5,%6,%7}, {%8,%9}, {%0,%1,%2,%3};"
        : "+f"(c[0]), "+f"(c[1]), "+f"(c[2]), "+f"(c[3])
        : "r"(a[0]), "r"(a[1]), "r"(a[2]), "r"(a[3]), "r"(b[0]), "r"(b[1]));
}

// ---------------------------------------------------------------------------
// Persistent split-bf16 HMMA GEMM: C[M,N] = A[M,K] @ B[N,K]^T (+row bias)
// K = 512 (8 chunks of BK=64). CTA = 128 threads (4 warps), tile 64m x 128n,
// warp tile 32x64. 2-stage cp.async pipeline, 48KB/stage -> 96KB/CTA
// -> 2 CTAs resident per SM (grid = 2*#SM, persistent over tiles).
// If Ohi != null: write split-bf16 output instead of fp32 C.
// ---------------------------------------------------------------------------
#define STAGE_BYTES 49152
#define OFF_AHI 0
#define OFF_ALO 8192
#define OFF_BHI 16384
#define OFF_BLO 32768
#define GEMM_SMEM (2 * STAGE_BYTES)
#define CHUNKS_PER_TILE 8    // K=512 / BK=64

__global__ __launch_bounds__(128, 2)
void mma_gemm_persistent(const __nv_bfloat16* __restrict__ Ahi,
                         const __nv_bfloat16* __restrict__ Alo,
                         const __nv_bfloat16* __restrict__ Bhi,
                         const __nv_bfloat16* __restrict__ Blo,
                         float* __restrict__ C,
                         int ntm, int ntn, int nb, int N, int K,
                         long long sA, long long sB, long long sC,
                         const float* __restrict__ bias,
                         __nv_bfloat16* __restrict__ Ohi,
                         __nv_bfloat16* __restrict__ Olo)
{
    extern __shared__ char smem[];
    const uint32_t sbase = smem_to_u32(smem);

    const int tid = threadIdx.x;
    const int wid = tid >> 5;
    const int lane = tid & 31;
    const int warp_m = wid >> 1;       // 0..1 (32 rows each)
    const int warp_n = wid & 1;        // 0..1 (64 cols each)

    const int ntiles = ntm * ntn * nb;
    const int my_ntiles = (ntiles - (int)blockIdx.x + (int)gridDim.x - 1) / (int)gridDim.x;
    if (my_ntiles <= 0) return;
    const int my_nchunks = my_ntiles * CHUNKS_PER_TILE;

    auto load_chunk = [&](int k) {
        const int t = k >> 3;
        const int tile_lin = (int)blockIdx.x + t * (int)gridDim.x;
        if (tile_lin >= ntiles) { CP_ASYNC_COMMIT(); return; }
        const int nx = tile_lin % ntn;
        const int rest = tile_lin / ntn;
        const int my = rest % ntm;
        const int b = rest / ntm;
        const int bm = my << 6;        // 64-row tiles
        const int bn = nx << 7;        // 128-col tiles
        const int k0 = (k & 7) << 6;
        const __nv_bfloat16* pAhi = Ahi + (long long)b * sA;
        const __nv_bfloat16* pAlo = Alo + (long long)b * sA;
        const __nv_bfloat16* pBhi = Bhi + (long long)b * sB;
        const __nv_bfloat16* pBlo = Blo + (long long)b * sB;
        const uint32_t sb = sbase + (uint32_t)(k & 1) * STAGE_BYTES;
        // A: 64 rows x 128B = 512 granules per limb
#pragma unroll
        for (int it = 0; it < 4; it++) {
            const int g = it * 128 + tid;
            const int row = g >> 3;
            const int gr = g & 7;
            const uint32_t sw = SMEM_SWIZZLE_128B(row * 128 + gr * 16);
            const long long aoff = (long long)(bm + row) * K + k0 + gr * 8;
            cp_async16(sb + OFF_AHI + sw, pAhi + aoff);
            cp_async16(sb + OFF_ALO + sw, pAlo + aoff);
        }
        // B: 128 rows x 128B = 1024 granules per limb
#pragma unroll
        for (int it = 0; it < 8; it++) {
            const int g = it * 128 + tid;
            const int row = g >> 3;
            const int gr = g & 7;
            const uint32_t sw = SMEM_SWIZZLE_128B(row * 128 + gr * 16);
            const long long boff = (long long)(bn + row) * K + k0 + gr * 8;
            cp_async16(sb + OFF_BHI + sw, pBhi + boff);
            cp_async16(sb + OFF_BLO + sw, pBlo + boff);
        }
        CP_ASYNC_COMMIT();
    };

    float acc[2][8][4];
#pragma unroll
    for (int i = 0; i < 2; i++)
#pragma unroll
        for (int j = 0; j < 8; j++)
#pragma unroll
            for (int r = 0; r < 4; r++) acc[i][j][r] = 0.0f;

    load_chunk(0);
    load_chunk(1);

    for (int k = 0; k < my_nchunks; k++) {
        CP_ASYNC_WAIT(1);
        __syncthreads();

        const uint32_t sb = sbase + (uint32_t)(k & 1) * STAGE_BYTES;
#pragma unroll
        for (int ks = 0; ks < 4; ks++) {
            uint32_t bhi[16], blo[16];
#pragma unroll
            for (int p = 0; p < 4; p++) {
                const int r = warp_n * 64 + p * 16 + ((lane >> 4) & 1) * 8 + (lane & 7);
                const int cb = ks * 32 + ((lane >> 3) & 1) * 16;
                const uint32_t adr = sb + OFF_BHI + SMEM_SWIZZLE_128B(r * 128 + cb);
                ldsm4(bhi + p * 4, adr);
                ldsm4(blo + p * 4, adr + (OFF_BLO - OFF_BHI));
            }
#pragma unroll
            for (int i = 0; i < 2; i++) {
                const int r = warp_m * 32 + i * 16 + ((lane >> 3) & 1) * 8 + (lane & 7);
                const int cb = ks * 32 + ((lane >> 4) & 1) * 16;
                const uint32_t adr = sb + OFF_AHI + SMEM_SWIZZLE_128B(r * 128 + cb);
                uint32_t ahi[4], alo[4];
                ldsm4(ahi, adr);
                ldsm4(alo, adr + (OFF_ALO - OFF_AHI));
#pragma unroll
                for (int j = 0; j < 8; j++) {
                    const uint32_t* bh = bhi + (j >> 1) * 4 + (j & 1) * 2;
                    const uint32_t* bl = blo + (j >> 1) * 4 + (j & 1) * 2;
                    mma_bf16(acc[i][j], ahi, bh);
                    mma_bf16(acc[i][j], ahi, bl);
                    mma_bf16(acc[i][j], alo, bh);
                }
            }
        }
        __syncthreads();
        load_chunk(k + 2);   // 2-stage: stage (k&1) free after barrier

        if ((k & 7) == 7) {
            const int t = k >> 3;
            const int tile_lin = (int)blockIdx.x + t * (int)gridDim.x;
            const int nx = tile_lin % ntn;
            const int rest = tile_lin / ntn;
            const int my = rest % ntm;
            const int b = rest / ntm;
            const int bm = my << 6;
            const int bn = nx << 7;
            if (Ohi == nullptr) {
                float* pC = C + (long long)b * sC;
#pragma unroll
                for (int i = 0; i < 2; i++) {
                    const int m0 = bm + warp_m * 32 + i * 16 + (lane >> 2);
                    const float bv0 = bias ? bias[m0] : 0.0f;
                    const float bv1 = bias ? bias[m0 + 8] : 0.0f;
#pragma unroll
                    for (int j = 0; j < 8; j++) {
                        const int n0 = bn + warp_n * 64 + j * 8 + (lane & 3) * 2;
                        float2 v0, v1;
                        v0.x = acc[i][j][0] + bv0;  v0.y = acc[i][j][1] + bv0;
                        v1.x = acc[i][j][2] + bv1;  v1.y = acc[i][j][3] + bv1;
                        *(float2*)(pC + (long long)m0 * N + n0) = v0;
                        *(float2*)(pC + (long long)(m0 + 8) * N + n0) = v1;
                        acc[i][j][0] = 0.0f; acc[i][j][1] = 0.0f;
                        acc[i][j][2] = 0.0f; acc[i][j][3] = 0.0f;
                    }
                }
            } else {
                __nv_bfloat16* pH = Ohi + (long long)b * sC;
                __nv_bfloat16* pL = Olo + (long long)b * sC;
#pragma unroll
                for (int i = 0; i < 2; i++) {
                    const int m0 = bm + warp_m * 32 + i * 16 + (lane >> 2);
#pragma unroll
                    for (int j = 0; j < 8; j++) {
                        const int n0 = bn + warp_n * 64 + j * 8 + (lane & 3) * 2;
#pragma unroll
                        for (int r = 0; r < 4; r++) {
                            const int mm = m0 + (r >> 1) * 8;
                            const int nn = n0 + (r & 1);
                            const float v = acc[i][j][r];
                            const __nv_bfloat16 hi = __float2bfloat16(v);
                            pH[(long long)mm * N + nn] = hi;
                            pL[(long long)mm * N + nn] = __float2bfloat16(v - __bfloat162float(hi));
                            acc[i][j][r] = 0.0f;
                        }
                    }
                }
            }
        }
    }
}

// ---------------------------------------------------------------------------
// Transpose + split-convert: in fp32 [R, L] -> out_hi/out_lo bf16 [L, R]
// ---------------------------------------------------------------------------
__global__ __launch_bounds__(256) void transpose_convert_kernel(
    const float* __restrict__ in,
    __nv_bfloat16* __restrict__ out_hi, __nv_bfloat16* __restrict__ out_lo,
    int R, int L, long long inStride, long long outStride)
{
    const int b = blockIdx.z;
    in += (long long)b * inStride;
    out_hi += (long long)b * outStride;
    out_lo += (long long)b * outStride;

    __shared__ float t[32][33];
    const int r0 = blockIdx.y * 32;
    const int c0 = blockIdx.x * 32;
    const int tx = threadIdx.x & 31;
    const int ty = threadIdx.x >> 5;

#pragma unroll
    for (int i = 0; i < 4; i++)
        t[ty + i * 8][tx] = in[(long long)(r0 + ty + i * 8) * L + c0 + tx];
    __syncthreads();
#pragma unroll
    for (int i = 0; i < 4; i++) {
        const float v = t[tx][ty + i * 8];
        const __nv_bfloat16 hi = __float2bfloat16(v);
        const float lo = v - __bfloat162float(hi);
        const long long o = (long long)(c0 + ty + i * 8) * R + r0 + tx;
        out_hi[o] = hi;
        out_lo[o] = __float2bfloat16(lo);
    }
}

// Plain split-convert
__global__ __launch_bounds__(256) void convert_split_kernel(
    const float* __restrict__ in,
    __nv_bfloat16* __restrict__ hi, __nv_bfloat16* __restrict__ lo, int n)
{
    const int i = blockIdx.x * blockDim.x + threadIdx.x;
    if (i < n) {
        const float v = in[i];
        const __nv_bfloat16 h = __float2bfloat16(v);
        hi[i] = h;
        lo[i] = __float2bfloat16(v - __bfloat162float(h));
    }
}

// ---------------------------------------------------------------------------
// Row softmax over L=4096 on k rows (rows 0..511 of g_kv per batch)
// ---------------------------------------------------------------------------
__global__ __launch_bounds__(256) void softmax_kernel()
{
    const int row = blockIdx.x;
    const int b = row >> 9;
    const int r = row & 511;
    float* p = g_kv + (long long)b * KV_ROWS * LDIM + (long long)r * LDIM;

    const int tid = threadIdx.x;
    __shared__ float red[256];

    float4 v[4];
#pragma unroll
    for (int i = 0; i < 4; i++)
        v[i] = *(const float4*)(p + i * 1024 + tid * 4);

    float vmax = -1e30f;
#pragma unroll
    for (int i = 0; i < 4; i++)
        vmax = fmaxf(vmax, fmaxf(fmaxf(v[i].x, v[i].y), fmaxf(v[i].z, v[i].w)));
    red[tid] = vmax;
    __syncthreads();
    for (int s = 128; s > 0; s >>= 1) {
        if (tid < s) red[tid] = fmaxf(red[tid], red[tid + s]);
        __syncthreads();
    }
    vmax = red[0];
    __syncthreads();

    float lsum = 0.0f;
#pragma unroll
    for (int i = 0; i < 4; i++) {
        v[i].x = expf(v[i].x - vmax); lsum += v[i].x;
        v[i].y = expf(v[i].y - vmax); lsum += v[i].y;
        v[i].z = expf(v[i].z - vmax); lsum += v[i].z;
        v[i].w = expf(v[i].w - vmax); lsum += v[i].w;
    }
    red[tid] = lsum;
    __syncthreads();
    for (int s = 128; s > 0; s >>= 1) {
        if (tid < s) red[tid] += red[tid + s];
        __syncthreads();
    }
    const float inv = 1.0f / red[0];

#pragma unroll
    for (int i = 0; i < 4; i++) {
        v[i].x *= inv; v[i].y *= inv; v[i].z *= inv; v[i].w *= inv;
        *(float4*)(p + i * 1024 + tid * 4) = v[i];
    }
}

// ---------------------------------------------------------------------------
// Context partials + reduce + fold (fp32)
// ---------------------------------------------------------------------------
__global__ __launch_bounds__(256) void context_partial_kernel()
{
    const int split = blockIdx.x;
    const int bh = blockIdx.y;
    const int b = bh >> 3, h = bh & 7;

    const float* kbase = g_kv + (long long)b * KV_ROWS * LDIM + (long long)(h * DHEAD) * LDIM;
    const float* vbase = g_kv + (long long)b * KV_ROWS * LDIM + (long long)(HID + h * DHEAD) * LDIM;

    __shared__ float Ks[64][65];
    __shared__ float Vs[64][65];

    const int tid = threadIdx.x;
    const int td = (tid >> 4) * 4;
    const int te = (tid & 15) * 4;

    float acc[4][4];
#pragma unroll
    for (int i = 0; i < 4; i++)
#pragma unroll
        for (int j = 0; j < 4; j++) acc[i][j] = 0.0f;

    const int chunk = LDIM / CSPLIT;
    for (int sub = 0; sub < chunk / 64; sub++) {
        const int n0 = split * chunk + sub * 64;
        for (int i = tid; i < 1024; i += 256) {
            const int r = i >> 4, c = (i & 15) * 4;
            float4 kv = *(const float4*)(kbase + (long long)r * LDIM + n0 + c);
            Ks[r][c] = kv.x; Ks[r][c + 1] = kv.y; Ks[r][c + 2] = kv.z; Ks[r][c + 3] = kv.w;
            float4 vv = *(const float4*)(vbase + (long long)r * LDIM + n0 + c);
            Vs[r][c] = vv.x; Vs[r][c + 1] = vv.y; Vs[r][c + 2] = vv.z; Vs[r][c + 3] = vv.w;
        }
        __syncthreads();

#pragma unroll 8
        for (int n = 0; n < 64; n++) {
            float kr[4], vr[4];
#pragma unroll
            for (int i = 0; i < 4; i++) kr[i] = Ks[td + i][n];
#pragma unroll
            for (int j = 0; j < 4; j++) vr[j] = Vs[te + j][n];
#pragma unroll
            for (int i = 0; i < 4; i++)
#pragma unroll
                for (int j = 0; j < 4; j++)
                    acc[i][j] = fmaf(kr[i], vr[j], acc[i][j]);
        }
        __syncthreads();
    }

    float* pout = g_part + ((long long)split * 64 + bh) * (DHEAD * DHEAD);
#pragma unroll
    for (int i = 0; i < 4; i++)
#pragma unroll
        for (int j = 0; j < 4; j++)
            pout[(td + i) * DHEAD + (te + j)] = acc[i][j];
}

__global__ __launch_bounds__(256) void reduce_ctx_kernel()
{
    const int i = blockIdx.x * blockDim.x + threadIdx.x;
    const int total = BATCH * HEADS * DHEAD * DHEAD;
    if (i < total) {
        float s = 0.0f;
#pragma unroll
        for (int sp = 0; sp < CSPLIT; sp++)
            s += g_part[(long long)sp * total + i];
        g_ctx[i] = s;
    }
}

// fold: writes split-bf16 M directly (M = w_out-folded context)
__global__ __launch_bounds__(256) void fold_kernel(const float* __restrict__ w_out)
{
    const int oc = blockIdx.x;
    const int bh = blockIdx.y;
    const int b = bh >> 3, h = bh & 7;

    __shared__ float cs[64][65];
    __shared__ float ws[64][65];

    const int tid = threadIdx.x;
    for (int i = tid; i < 4096; i += 256) {
        const int d = i >> 6, e = i & 63;
        cs[d][e] = g_ctx[((long long)bh * 64 + d) * 64 + e];
    }
    for (int i = tid; i < 4096; i += 256) {
        const int r = i >> 6, e = i & 63;
        ws[r][e] = w_out[(long long)(oc * 64 + r) * CDIM + h * 64 + e];
    }
    __syncthreads();

    const int d = tid & 63;
    const int r0 = (tid >> 6) * 16;
    for (int rr = 0; rr < 16; rr++) {
        float s = 0.0f;
#pragma unroll 8
        for (int e = 0; e < 64; e++)
            s = fmaf(ws[r0 + rr][e], cs[d][e], s);
        const long long o = ((long long)b * HID + oc * 64 + r0 + rr) * HID + h * 64 + d;
        const __nv_bfloat16 hi = __float2bfloat16(s);
        g_M_hi[o] = hi;
        g_M_lo[o] = __float2bfloat16(s - __bfloat162float(hi));
    }
}

// ---------------------------------------------------------------------------
extern "C" void kernel_launch(void* const* d_in, const int* in_sizes, int n_in,
                              void* d_out, int out_size)
{
    const float* x     = (const float*)d_in[0];   // [8, 512, 4096]
    const float* w_qkv = (const float*)d_in[1];   // [1536, 512]
    const float* w_out = (const float*)d_in[2];   // [512, 512]
    const float* b_out = (const float*)d_in[3];   // [512]
    float* out = (float*)d_out;                   // [8, 512, 4096]

    float *p_kv;
    __nv_bfloat16 *p_xthi, *p_xtlo, *p_whi, *p_wlo, *p_wqThi, *p_wqTlo;
    __nv_bfloat16 *p_Mhi, *p_Mlo, *p_Nhi, *p_Nlo;
    cudaGetSymbolAddress((void**)&p_kv, g_kv);
    cudaGetSymbolAddress((void**)&p_xthi, g_xt_hi);
    cudaGetSymbolAddress((void**)&p_xtlo, g_xt_lo);
    cudaGetSymbolAddress((void**)&p_whi, g_w_hi);
    cudaGetSymbolAddress((void**)&p_wlo, g_w_lo);
    cudaGetSymbolAddress((void**)&p_wqThi, g_wqT_hi);
    cudaGetSymbolAddress((void**)&p_wqTlo, g_wqT_lo);
    cudaGetSymbolAddress((void**)&p_Mhi, g_M_hi);
    cudaGetSymbolAddress((void**)&p_Mlo, g_M_lo);
    cudaGetSymbolAddress((void**)&p_Nhi, g_N_hi);
    cudaGetSymbolAddress((void**)&p_Nlo, g_N_lo);

    int nsm = 148;
    cudaDeviceGetAttribute(&nsm, cudaDevAttrMultiProcessorCount, 0);
    const int grid = 2 * nsm;

    cudaFuncSetAttribute(mma_gemm_persistent,
                         cudaFuncAttributeMaxDynamicSharedMemorySize, GEMM_SMEM);

    // 0) split-convert W (all rows); transpose+split x; transpose+split Wq
    convert_split_kernel<<<(QKV_ROWS * CDIM + 255) / 256, 256>>>(w_qkv, p_whi, p_wlo, QKV_ROWS * CDIM);
    transpose_convert_kernel<<<dim3(LDIM / 32, CDIM / 32, BATCH), 256>>>(
        x, p_xthi, p_xtlo, CDIM, LDIM,
        (long long)CDIM * LDIM, (long long)LDIM * CDIM);
    transpose_convert_kernel<<<dim3(CDIM / 32, HID / 32, 1), 256>>>(
        w_qkv, p_wqThi, p_wqTlo, HID, CDIM, 0LL, 0LL);

    // 1) kv = W_kv @ x  (rows 512..1535 of W)
    mma_gemm_persistent<<<grid, 128, GEMM_SMEM>>>(
        p_whi + (size_t)HID * CDIM, p_wlo + (size_t)HID * CDIM,
        p_xthi, p_xtlo, p_kv,
        KV_ROWS / 64, LDIM / 128, BATCH, LDIM, CDIM,
        0LL, (long long)LDIM * CDIM, (long long)KV_ROWS * LDIM, nullptr,
        nullptr, nullptr);

    // 2) softmax over L on k rows
    softmax_kernel<<<BATCH * HID, 256>>>();

    // 3) context partials + deterministic reduce
    context_partial_kernel<<<dim3(CSPLIT, BATCH * HEADS), 256>>>();
    {
        const int total = BATCH * HEADS * DHEAD * DHEAD;
        reduce_ctx_kernel<<<(total + 255) / 256, 256>>>();
    }

    // 4) fold w_out with context -> split-bf16 M directly
    fold_kernel<<<dim3(8, BATCH * HEADS), 256>>>(w_out);

    // 5) N = M @ Wq  (split-bf16 in, split-bf16 out)
    mma_gemm_persistent<<<grid, 128, GEMM_SMEM>>>(
        p_Mhi, p_Mlo, p_wqThi, p_wqTlo, nullptr,
        HID / 64, HID / 128, BATCH, HID, CDIM,
        (long long)HID * HID, 0LL, (long long)HID * HID, nullptr,
        p_Nhi, p_Nlo);

    // 6) out = N @ x + b_out
    mma_gemm_persistent<<<grid, 128, GEMM_SMEM>>>(
        p_Nhi, p_Nlo, p_xthi, p_xtlo, out,
        HID / 64, LDIM / 128, BATCH, LDIM, CDIM,
        (long long)HID * HID, (long long)LDIM * CDIM, (long long)HID * LDIM, b_out,
        nullptr, nullptr);
}